// round 3
// baseline (speedup 1.0000x reference)
#include <cuda_runtime.h>
#include <math.h>

#define Bb 8
#define Nn 1024
#define Hh 128
#define MSGd 128
#define Ll 5
#define TGT 12
#define NLAYERS 3
#define NODES (Bb * Nn) /* 8192 */
#define TW 64

// ---------------- scratch (single __device__ buffer, no allocations) ----------------
#define OFF_H      0
#define OFF_H0     (OFF_H + NODES * 128)
#define OFF_MASK   (OFF_H0 + NODES * 128)
#define OFF_RMASK  (OFF_MASK + NODES)
#define OFF_HCAT   (OFF_RMASK + NODES)
#define OFF_AGG    (OFF_HCAT + NODES * 640)
#define OFF_GI     (OFF_AGG + NODES * 128)
#define OFF_GH     (OFF_GI + NODES * 384)
#define OFF_PART   (OFF_GH + NODES * 384)
#define SCRATCH_FLOATS (OFF_PART + Bb * 16 * TGT)

__device__ float d_scratch[SCRATCH_FLOATS];

// ---------------- init: pad h_in -> h0/h, compute masks ----------------
__global__ void init_pad(const float* __restrict__ h_in, float* __restrict__ h,
                         float* __restrict__ h0) {
    int idx = blockIdx.x * blockDim.x + threadIdx.x;  // NODES*128
    int node = idx >> 7;
    int j = idx & 127;
    float v = (j < 64) ? h_in[node * 64 + j] : 0.f;
    h0[idx] = v;
    h[idx] = v;
}

__global__ void init_mask(const float* __restrict__ h_in, float* __restrict__ mask,
                          float* __restrict__ rmask) {
    int node = blockIdx.x * blockDim.x + threadIdx.x;
    float sa = 0.f, s = 0.f;
    const float* row = h_in + node * 64;
    for (int j = 0; j < 64; j++) {
        float v = row[j];
        sa += fabsf(v);
        s += v;
    }
    mask[node] = (sa > 0.f) ? 1.f : 0.f;
    rmask[node] = (s > 0.f) ? 1.f : 0.f;
}

// ---------------- generic GEMM, K=128: C[64x128 tile] = A[M,128] @ Bslice[128,128] ----------------
__global__ void gemm_k128(const float* __restrict__ A, const float* __restrict__ B,
                          float* __restrict__ C, int ldb, int ldc, int bstride) {
    extern __shared__ float sm[];
    float* As = sm;             // 64*128
    float* Bs = sm + 64 * 128;  // 128*128
    int t = threadIdx.x;
    const float* Bp = B + blockIdx.y * bstride;
    int row0 = blockIdx.x * 64;
    int cbase = blockIdx.y * 128;

#pragma unroll
    for (int i = 0; i < 8; i++) {
        int f = t + i * 256;
        int r = f >> 5;
        int c4 = (f & 31) << 2;
        *(float4*)&As[r * 128 + c4] = *(const float4*)&A[(size_t)(row0 + r) * 128 + c4];
    }
#pragma unroll
    for (int i = 0; i < 16; i++) {
        int f = t + i * 256;
        int k = f >> 5;
        int c4 = (f & 31) << 2;
        *(float4*)&Bs[k * 128 + c4] = *(const float4*)&Bp[(size_t)k * ldb + c4];
    }
    __syncthreads();

    int tcol = (t & 31) << 2;
    int trow = (t >> 5) << 3;
    float4 acc[8];
#pragma unroll
    for (int i = 0; i < 8; i++) acc[i] = make_float4(0.f, 0.f, 0.f, 0.f);

#pragma unroll 2
    for (int k = 0; k < 128; k += 4) {
        float4 b0 = *(float4*)&Bs[(k + 0) * 128 + tcol];
        float4 b1 = *(float4*)&Bs[(k + 1) * 128 + tcol];
        float4 b2 = *(float4*)&Bs[(k + 2) * 128 + tcol];
        float4 b3 = *(float4*)&Bs[(k + 3) * 128 + tcol];
#pragma unroll
        for (int i = 0; i < 8; i++) {
            float4 a = *(float4*)&As[(trow + i) * 128 + k];
            acc[i].x += a.x * b0.x; acc[i].y += a.x * b0.y; acc[i].z += a.x * b0.z; acc[i].w += a.x * b0.w;
            acc[i].x += a.y * b1.x; acc[i].y += a.y * b1.y; acc[i].z += a.y * b1.z; acc[i].w += a.y * b1.w;
            acc[i].x += a.z * b2.x; acc[i].y += a.z * b2.y; acc[i].z += a.z * b2.z; acc[i].w += a.z * b2.w;
            acc[i].x += a.w * b3.x; acc[i].y += a.w * b3.y; acc[i].z += a.w * b3.z; acc[i].w += a.w * b3.w;
        }
    }

#pragma unroll
    for (int i = 0; i < 8; i++) {
        *(float4*)&C[(size_t)(row0 + trow + i) * ldc + cbase + tcol] = acc[i];
    }
}

// ---------------- gather: agg[b,v,o] = sum_w g[b,v,w] * Hcat[b,w,e[b,v,w],o] ----------------
__global__ void gather_k(const float* __restrict__ g, const int* __restrict__ e,
                         const float* __restrict__ Hcat, float* __restrict__ agg) {
    extern __shared__ float sm[];
    float* HcS = sm;                               // [TW][640]
    float2* geS = (float2*)(sm + TW * 640);        // [64][TW]  {g, int_as_float(lab*128)}
    int t = threadIdx.x;
    int b = blockIdx.y;
    int v0 = blockIdx.x * 64;
    int lane = t & 31;
    int warp = t >> 5;
    int lane4 = lane << 2;

    float4 acc[8];
#pragma unroll
    for (int r = 0; r < 8; r++) acc[r] = make_float4(0.f, 0.f, 0.f, 0.f);

    const float* gB = g + (size_t)b * Nn * Nn;
    const int* eB = e + (size_t)b * Nn * Nn;
    const float* HcB = Hcat + (size_t)b * Nn * 640;

    for (int w0 = 0; w0 < Nn; w0 += TW) {
#pragma unroll
        for (int i = 0; i < 16; i++) {
            int f = t + i * 256;
            int r = f >> 6;
            int w = f & 63;
            size_t gidx = (size_t)(v0 + r) * Nn + w0 + w;
            float gv = gB[gidx];
            int lab = eB[gidx];
            geS[r * TW + w] = make_float2(gv, __int_as_float(lab << 7));
        }
        const float4* src = (const float4*)&HcB[(size_t)w0 * 640];
        float4* dst = (float4*)HcS;
#pragma unroll
        for (int i = 0; i < 40; i++) {
            dst[t + i * 256] = src[t + i * 256];
        }
        __syncthreads();

#pragma unroll 2
        for (int w = 0; w < TW; w++) {
            const float* Hrow = &HcS[w * 640 + lane4];
#pragma unroll
            for (int r = 0; r < 8; r++) {
                float2 ge = geS[(warp * 8 + r) * TW + w];
                int off = __float_as_int(ge.y);
                float4 m = *(const float4*)(Hrow + off);
                acc[r].x += ge.x * m.x;
                acc[r].y += ge.x * m.y;
                acc[r].z += ge.x * m.z;
                acc[r].w += ge.x * m.w;
            }
        }
        __syncthreads();
    }

#pragma unroll
    for (int r = 0; r < 8; r++) {
        *(float4*)&agg[((size_t)b * Nn + v0 + warp * 8 + r) * 128 + lane4] = acc[r];
    }
}

// ---------------- GRU elementwise ----------------
__global__ void gru_elem(const float* __restrict__ gi, const float* __restrict__ gh,
                         const float* __restrict__ bi, const float* __restrict__ bh,
                         float* __restrict__ h, const float* __restrict__ mask) {
    int idx = blockIdx.x * blockDim.x + threadIdx.x;  // NODES*128
    int node = idx >> 7;
    int j = idx & 127;
    size_t base = (size_t)node * 384;
    float ir = gi[base + j] + bi[j];
    float iz = gi[base + 128 + j] + bi[128 + j];
    float in_ = gi[base + 256 + j] + bi[256 + j];
    float hr = gh[base + j] + bh[j];
    float hz = gh[base + 128 + j] + bh[128 + j];
    float hn = gh[base + 256 + j] + bh[256 + j];
    float r = 1.f / (1.f + expf(-(ir + hr)));
    float z = 1.f / (1.f + expf(-(iz + hz)));
    float n = tanhf(in_ + r * hn);
    float hv = h[idx];
    h[idx] = ((1.f - z) * n + z * hv) * mask[node];
}

// ---------------- readout stage 1 ----------------
__global__ void readout1(const float* __restrict__ h, const float* __restrict__ h0,
                         const float* __restrict__ rmask, const float* __restrict__ Wg,
                         const float* __restrict__ bg, const float* __restrict__ Wo,
                         const float* __restrict__ bo, float* __restrict__ partial) {
    __shared__ float red[64][TGT];
    int b = blockIdx.y;
    int node = b * Nn + blockIdx.x * 64 + threadIdx.x;
    const float* hT = &h[(size_t)node * 128];
    const float* hz = &h0[(size_t)node * 128];
    float rm = rmask[node];

    float sg[TGT], so[TGT];
#pragma unroll
    for (int t = 0; t < TGT; t++) { sg[t] = bg[t]; so[t] = bo[t]; }

    for (int j = 0; j < 128; j++) {
        float a = hT[j];
        float c = hz[j];
#pragma unroll
        for (int t = 0; t < TGT; t++) {
            sg[t] += a * Wg[j * TGT + t] + c * Wg[(128 + j) * TGT + t];
            so[t] += a * Wo[j * TGT + t];
        }
    }
#pragma unroll
    for (int t = 0; t < TGT; t++) {
        float gate = 1.f / (1.f + expf(-sg[t]));
        red[threadIdx.x][t] = gate * so[t] * rm;
    }
    __syncthreads();
    if (threadIdx.x < TGT) {
        int t = threadIdx.x;
        float s = 0.f;
        for (int v = 0; v < 64; v++) s += red[v][t];
        partial[((size_t)b * 16 + blockIdx.x) * TGT + t] = s;
    }
}

__global__ void readout2(const float* __restrict__ partial, float* __restrict__ out) {
    int i = threadIdx.x;
    if (i < Bb * TGT) {
        int b = i / TGT, t = i % TGT;
        float s = 0.f;
        for (int c = 0; c < 16; c++) s += partial[((size_t)b * 16 + c) * TGT + t];
        out[i] = s;
    }
}

// ---------------- launch ----------------
extern "C" void kernel_launch(void* const* d_in, const int* in_sizes, int n_in,
                              void* d_out, int out_size) {
    const float* g = (const float*)d_in[0];
    const float* h_in = (const float*)d_in[1];
    const int* e = (const int*)d_in[2];
    const float* A = (const float*)d_in[3];
    const float* Wi = (const float*)d_in[4];
    const float* Wh = (const float*)d_in[5];
    const float* bi = (const float*)d_in[6];
    const float* bh = (const float*)d_in[7];
    const float* Wg = (const float*)d_in[8];
    const float* bg = (const float*)d_in[9];
    const float* Wo = (const float*)d_in[10];
    const float* bo = (const float*)d_in[11];
    float* out = (float*)d_out;

    float* base;
    cudaGetSymbolAddress((void**)&base, d_scratch);
    float* h = base + OFF_H;
    float* h0 = base + OFF_H0;
    float* mask = base + OFF_MASK;
    float* rmask = base + OFF_RMASK;
    float* Hcat = base + OFF_HCAT;
    float* agg = base + OFF_AGG;
    float* gi = base + OFF_GI;
    float* gh = base + OFF_GH;
    float* partial = base + OFF_PART;

    const int GEMM_SMEM = (64 * 128 + 128 * 128) * 4;            // 96KB
    const int GATH_SMEM = TW * 640 * 4 + 64 * TW * 8;            // 192KB
    cudaFuncSetAttribute(gemm_k128, cudaFuncAttributeMaxDynamicSharedMemorySize, GEMM_SMEM);
    cudaFuncSetAttribute(gather_k, cudaFuncAttributeMaxDynamicSharedMemorySize, GATH_SMEM);

    init_pad<<<NODES * 128 / 256, 256>>>(h_in, h, h0);
    init_mask<<<NODES / 128, 128>>>(h_in, mask, rmask);

    for (int layer = 0; layer < NLAYERS; layer++) {
        gemm_k128<<<dim3(NODES / 64, Ll), 256, GEMM_SMEM>>>(h, A, Hcat, 128, 640, 128 * 128);
        gather_k<<<dim3(Nn / 64, Bb), 256, GATH_SMEM>>>(g, e, Hcat, agg);
        gemm_k128<<<dim3(NODES / 64, 3), 256, GEMM_SMEM>>>(agg, Wi, gi, 384, 384, 128);
        gemm_k128<<<dim3(NODES / 64, 3), 256, GEMM_SMEM>>>(h, Wh, gh, 384, 384, 128);
        gru_elem<<<NODES * 128 / 256, 256>>>(gi, gh, bi, bh, h, mask);
    }

    readout1<<<dim3(16, Bb), 64>>>(h, h0, rmask, Wg, bg, Wo, bo, partial);
    readout2<<<1, 128>>>(partial, out);
}

// round 5
// speedup vs baseline: 1.3324x; 1.3324x over previous
#include <cuda_runtime.h>
#include <cuda_fp16.h>
#include <math.h>

#define Bb 8
#define Nn 1024
#define Ll 5
#define TGT 12
#define NLAYERS 3
#define NODES (Bb * Nn) /* 8192 */
#define TW 64

// ---------------- scratch (single __device__ buffer, no allocations) ----------------
#define OFF_H      0
#define OFF_H0     (OFF_H + NODES * 128)
#define OFF_MASK   (OFF_H0 + NODES * 128)
#define OFF_RMASK  (OFF_MASK + NODES)
#define OFF_HCAT   (OFF_RMASK + NODES)              /* used as __half[NODES*640] */
#define OFF_AGG0   (OFF_HCAT + NODES * 640)
#define OFF_AGG1   (OFF_AGG0 + NODES * 128)
#define OFF_GI     (OFF_AGG1 + NODES * 128)
#define OFF_GH     (OFF_GI + NODES * 384)
#define OFF_PART   (OFF_GH + NODES * 384)
#define SCRATCH_FLOATS (OFF_PART + Bb * 16 * TGT)

__device__ float d_scratch[SCRATCH_FLOATS];

// ---------------- init ----------------
__global__ void init_pad(const float* __restrict__ h_in, float* __restrict__ h,
                         float* __restrict__ h0) {
    int idx = blockIdx.x * blockDim.x + threadIdx.x;
    int node = idx >> 7;
    int j = idx & 127;
    float v = (j < 64) ? h_in[node * 64 + j] : 0.f;
    h0[idx] = v;
    h[idx] = v;
}

__global__ void init_mask(const float* __restrict__ h_in, float* __restrict__ mask,
                          float* __restrict__ rmask) {
    int node = blockIdx.x * blockDim.x + threadIdx.x;
    float sa = 0.f, s = 0.f;
    const float* row = h_in + node * 64;
    for (int j = 0; j < 64; j++) {
        float v = row[j];
        sa += fabsf(v);
        s += v;
    }
    mask[node] = (sa > 0.f) ? 1.f : 0.f;
    rmask[node] = (s > 0.f) ? 1.f : 0.f;
}

// ---------------- fp32-out GEMM, K=128 (GRU gates) ----------------
__global__ void gemm_k128(const float* __restrict__ A, const float* __restrict__ B,
                          float* __restrict__ C, int ldb, int ldc, int bstride) {
    extern __shared__ float sm[];
    float* As = sm;             // 64*128
    float* Bs = sm + 64 * 128;  // 128*128
    int t = threadIdx.x;
    const float* Bp = B + blockIdx.y * bstride;
    int row0 = blockIdx.x * 64;
    int cbase = blockIdx.y * 128;

#pragma unroll
    for (int i = 0; i < 8; i++) {
        int f = t + i * 256;
        int r = f >> 5;
        int c4 = (f & 31) << 2;
        *(float4*)&As[r * 128 + c4] = *(const float4*)&A[(size_t)(row0 + r) * 128 + c4];
    }
#pragma unroll
    for (int i = 0; i < 16; i++) {
        int f = t + i * 256;
        int k = f >> 5;
        int c4 = (f & 31) << 2;
        *(float4*)&Bs[k * 128 + c4] = *(const float4*)&Bp[(size_t)k * ldb + c4];
    }
    __syncthreads();

    int tcol = (t & 31) << 2;
    int trow = (t >> 5) << 3;
    float4 acc[8];
#pragma unroll
    for (int i = 0; i < 8; i++) acc[i] = make_float4(0.f, 0.f, 0.f, 0.f);

#pragma unroll 2
    for (int k = 0; k < 128; k += 4) {
        float4 b0 = *(float4*)&Bs[(k + 0) * 128 + tcol];
        float4 b1 = *(float4*)&Bs[(k + 1) * 128 + tcol];
        float4 b2 = *(float4*)&Bs[(k + 2) * 128 + tcol];
        float4 b3 = *(float4*)&Bs[(k + 3) * 128 + tcol];
#pragma unroll
        for (int i = 0; i < 8; i++) {
            float4 a = *(float4*)&As[(trow + i) * 128 + k];
            acc[i].x += a.x * b0.x; acc[i].y += a.x * b0.y; acc[i].z += a.x * b0.z; acc[i].w += a.x * b0.w;
            acc[i].x += a.y * b1.x; acc[i].y += a.y * b1.y; acc[i].z += a.y * b1.z; acc[i].w += a.y * b1.w;
            acc[i].x += a.z * b2.x; acc[i].y += a.z * b2.y; acc[i].z += a.z * b2.z; acc[i].w += a.z * b2.w;
            acc[i].x += a.w * b3.x; acc[i].y += a.w * b3.y; acc[i].z += a.w * b3.z; acc[i].w += a.w * b3.w;
        }
    }

#pragma unroll
    for (int i = 0; i < 8; i++) {
        *(float4*)&C[(size_t)(row0 + trow + i) * ldc + cbase + tcol] = acc[i];
    }
}

// ---------------- fp16-out GEMM, K=128 (messages -> Hcat in half) ----------------
__global__ void gemm_k128_h(const float* __restrict__ A, const float* __restrict__ B,
                            __half* __restrict__ C, int ldb, int bstride) {
    extern __shared__ float sm[];
    float* As = sm;
    float* Bs = sm + 64 * 128;
    int t = threadIdx.x;
    const float* Bp = B + blockIdx.y * bstride;
    int row0 = blockIdx.x * 64;
    int cbase = blockIdx.y * 128;

#pragma unroll
    for (int i = 0; i < 8; i++) {
        int f = t + i * 256;
        int r = f >> 5;
        int c4 = (f & 31) << 2;
        *(float4*)&As[r * 128 + c4] = *(const float4*)&A[(size_t)(row0 + r) * 128 + c4];
    }
#pragma unroll
    for (int i = 0; i < 16; i++) {
        int f = t + i * 256;
        int k = f >> 5;
        int c4 = (f & 31) << 2;
        *(float4*)&Bs[k * 128 + c4] = *(const float4*)&Bp[(size_t)k * ldb + c4];
    }
    __syncthreads();

    int tcol = (t & 31) << 2;
    int trow = (t >> 5) << 3;
    float4 acc[8];
#pragma unroll
    for (int i = 0; i < 8; i++) acc[i] = make_float4(0.f, 0.f, 0.f, 0.f);

#pragma unroll 2
    for (int k = 0; k < 128; k += 4) {
        float4 b0 = *(float4*)&Bs[(k + 0) * 128 + tcol];
        float4 b1 = *(float4*)&Bs[(k + 1) * 128 + tcol];
        float4 b2 = *(float4*)&Bs[(k + 2) * 128 + tcol];
        float4 b3 = *(float4*)&Bs[(k + 3) * 128 + tcol];
#pragma unroll
        for (int i = 0; i < 8; i++) {
            float4 a = *(float4*)&As[(trow + i) * 128 + k];
            acc[i].x += a.x * b0.x; acc[i].y += a.x * b0.y; acc[i].z += a.x * b0.z; acc[i].w += a.x * b0.w;
            acc[i].x += a.y * b1.x; acc[i].y += a.y * b1.y; acc[i].z += a.y * b1.z; acc[i].w += a.y * b1.w;
            acc[i].x += a.z * b2.x; acc[i].y += a.z * b2.y; acc[i].z += a.z * b2.z; acc[i].w += a.z * b2.w;
            acc[i].x += a.w * b3.x; acc[i].y += a.w * b3.y; acc[i].z += a.w * b3.z; acc[i].w += a.w * b3.w;
        }
    }

#pragma unroll
    for (int i = 0; i < 8; i++) {
        __half2 p0 = __floats2half2_rn(acc[i].x, acc[i].y);
        __half2 p1 = __floats2half2_rn(acc[i].z, acc[i].w);
        uint2 u;
        u.x = *(unsigned int*)&p0;
        u.y = *(unsigned int*)&p1;
        *(uint2*)&C[(size_t)(row0 + trow + i) * 640 + cbase + tcol] = u;
    }
}

// ---------------- gather (half Hcat, w-split): agg_h[b,v,o] = sum_{w in half} g*Hcat[e] ----------------
// grid (16, Bb, 2), block 256. smem = 64*640*2 (HcS half) + 64*64*8 (geS) = 112KB -> 2 CTAs/SM.
__global__ void gather_h(const float* __restrict__ g, const int* __restrict__ e,
                         const __half* __restrict__ Hcat, float* __restrict__ agg) {
    extern __shared__ char smc[];
    __half* HcS = (__half*)smc;                       // [TW][640] halves
    float2* geS = (float2*)(smc + TW * 640 * 2);      // [64][TW]  {g, int_as_float(lab*128)}
    int t = threadIdx.x;
    int b = blockIdx.y;
    int v0 = blockIdx.x * 64;
    int wbase = blockIdx.z * (Nn / 2);
    int lane = t & 31;
    int warp = t >> 5;
    int lane4 = lane << 2;

    float4 acc[8];
#pragma unroll
    for (int r = 0; r < 8; r++) acc[r] = make_float4(0.f, 0.f, 0.f, 0.f);

    const float* gB = g + (size_t)b * Nn * Nn;
    const int* eB = e + (size_t)b * Nn * Nn;
    const __half* HcB = Hcat + (size_t)b * Nn * 640;

    for (int w0 = wbase; w0 < wbase + Nn / 2; w0 += TW) {
        // g/e tile: 64 rows x TW
#pragma unroll
        for (int i = 0; i < 16; i++) {
            int f = t + i * 256;
            int r = f >> 6;
            int w = f & 63;
            size_t gidx = (size_t)(v0 + r) * Nn + w0 + w;
            float gv = gB[gidx];
            int lab = eB[gidx];
            geS[r * TW + w] = make_float2(gv, __int_as_float(lab << 7));
        }
        // Hcat tile copy: TW*640 halves = 81920B = 5120 uint4
        const uint4* src = (const uint4*)(HcB + (size_t)w0 * 640);
        uint4* dst = (uint4*)HcS;
#pragma unroll
        for (int i = 0; i < 20; i++) {
            dst[t + i * 256] = src[t + i * 256];
        }
        __syncthreads();

#pragma unroll 2
        for (int w = 0; w < TW; w++) {
            const __half* base = HcS + w * 640 + lane4;
#pragma unroll
            for (int r = 0; r < 8; r++) {
                float2 ge = geS[(warp * 8 + r) * TW + w];
                int off = __float_as_int(ge.y);
                uint2 mv = *(const uint2*)(base + off);
                float2 f0 = __half22float2(*(__half2*)&mv.x);
                float2 f1 = __half22float2(*(__half2*)&mv.y);
                acc[r].x += ge.x * f0.x;
                acc[r].y += ge.x * f0.y;
                acc[r].z += ge.x * f1.x;
                acc[r].w += ge.x * f1.y;
            }
        }
        __syncthreads();
    }

#pragma unroll
    for (int r = 0; r < 8; r++) {
        *(float4*)&agg[(size_t)blockIdx.z * NODES * 128 +
                       ((size_t)b * Nn + v0 + warp * 8 + r) * 128 + lane4] = acc[r];
    }
}

// ---------------- sum the two w-halves ----------------
__global__ void agg_add(float* __restrict__ a0, const float* __restrict__ a1) {
    int idx = blockIdx.x * blockDim.x + threadIdx.x;
    a0[idx] += a1[idx];
}

// ---------------- GRU elementwise ----------------
__global__ void gru_elem(const float* __restrict__ gi, const float* __restrict__ gh,
                         const float* __restrict__ bi, const float* __restrict__ bh,
                         float* __restrict__ h, const float* __restrict__ mask) {
    int idx = blockIdx.x * blockDim.x + threadIdx.x;
    int node = idx >> 7;
    int j = idx & 127;
    size_t base = (size_t)node * 384;
    float ir = gi[base + j] + bi[j];
    float iz = gi[base + 128 + j] + bi[128 + j];
    float in_ = gi[base + 256 + j] + bi[256 + j];
    float hr = gh[base + j] + bh[j];
    float hz = gh[base + 128 + j] + bh[128 + j];
    float hn = gh[base + 256 + j] + bh[256 + j];
    float r = 1.f / (1.f + expf(-(ir + hr)));
    float z = 1.f / (1.f + expf(-(iz + hz)));
    float n = tanhf(in_ + r * hn);
    float hv = h[idx];
    h[idx] = ((1.f - z) * n + z * hv) * mask[node];
}

// ---------------- readout ----------------
__global__ void readout1(const float* __restrict__ h, const float* __restrict__ h0,
                         const float* __restrict__ rmask, const float* __restrict__ Wg,
                         const float* __restrict__ bg, const float* __restrict__ Wo,
                         const float* __restrict__ bo, float* __restrict__ partial) {
    __shared__ float red[64][TGT];
    int b = blockIdx.y;
    int node = b * Nn + blockIdx.x * 64 + threadIdx.x;
    const float* hT = &h[(size_t)node * 128];
    const float* hz = &h0[(size_t)node * 128];
    float rm = rmask[node];

    float sg[TGT], so[TGT];
#pragma unroll
    for (int t = 0; t < TGT; t++) { sg[t] = bg[t]; so[t] = bo[t]; }

    for (int j = 0; j < 128; j++) {
        float a = hT[j];
        float c = hz[j];
#pragma unroll
        for (int t = 0; t < TGT; t++) {
            sg[t] += a * Wg[j * TGT + t] + c * Wg[(128 + j) * TGT + t];
            so[t] += a * Wo[j * TGT + t];
        }
    }
#pragma unroll
    for (int t = 0; t < TGT; t++) {
        float gate = 1.f / (1.f + expf(-sg[t]));
        red[threadIdx.x][t] = gate * so[t] * rm;
    }
    __syncthreads();
    if (threadIdx.x < TGT) {
        int t = threadIdx.x;
        float s = 0.f;
        for (int v = 0; v < 64; v++) s += red[v][t];
        partial[((size_t)b * 16 + blockIdx.x) * TGT + t] = s;
    }
}

__global__ void readout2(const float* __restrict__ partial, float* __restrict__ out) {
    int i = threadIdx.x;
    if (i < Bb * TGT) {
        int b = i / TGT, t = i % TGT;
        float s = 0.f;
        for (int c = 0; c < 16; c++) s += partial[((size_t)b * 16 + c) * TGT + t];
        out[i] = s;
    }
}

// ---------------- launch ----------------
extern "C" void kernel_launch(void* const* d_in, const int* in_sizes, int n_in,
                              void* d_out, int out_size) {
    const float* g = (const float*)d_in[0];
    const float* h_in = (const float*)d_in[1];
    const int* e = (const int*)d_in[2];
    const float* A = (const float*)d_in[3];
    const float* Wi = (const float*)d_in[4];
    const float* Wh = (const float*)d_in[5];
    const float* bi = (const float*)d_in[6];
    const float* bh = (const float*)d_in[7];
    const float* Wg = (const float*)d_in[8];
    const float* bg = (const float*)d_in[9];
    const float* Wo = (const float*)d_in[10];
    const float* bo = (const float*)d_in[11];
    float* out = (float*)d_out;

    float* base;
    cudaGetSymbolAddress((void**)&base, d_scratch);
    float* h = base + OFF_H;
    float* h0 = base + OFF_H0;
    float* mask = base + OFF_MASK;
    float* rmask = base + OFF_RMASK;
    __half* Hcat = (__half*)(base + OFF_HCAT);
    float* agg0 = base + OFF_AGG0;
    float* gi = base + OFF_GI;
    float* gh = base + OFF_GH;
    float* partial = base + OFF_PART;

    const int GEMM_SMEM = (64 * 128 + 128 * 128) * 4;       // 96KB
    const int GATH_SMEM = TW * 640 * 2 + 64 * TW * 8;       // 112KB -> 2 CTAs/SM
    cudaFuncSetAttribute(gemm_k128, cudaFuncAttributeMaxDynamicSharedMemorySize, GEMM_SMEM);
    cudaFuncSetAttribute(gemm_k128_h, cudaFuncAttributeMaxDynamicSharedMemorySize, GEMM_SMEM);
    cudaFuncSetAttribute(gather_h, cudaFuncAttributeMaxDynamicSharedMemorySize, GATH_SMEM);

    init_pad<<<NODES * 128 / 256, 256>>>(h_in, h, h0);
    init_mask<<<NODES / 128, 128>>>(h_in, mask, rmask);

    for (int layer = 0; layer < NLAYERS; layer++) {
        // messages: Hcat[node][l*128+o] = h[node] @ A[l]  (fp16 output)
        gemm_k128_h<<<dim3(NODES / 64, Ll), 256, GEMM_SMEM>>>(h, A, Hcat, 128, 128 * 128);
        // gather over two w-halves
        gather_h<<<dim3(Nn / 64, Bb, 2), 256, GATH_SMEM>>>(g, e, Hcat, agg0);
        agg_add<<<NODES * 128 / 256, 256>>>(agg0, agg0 + (size_t)NODES * 128);
        // GRU gate pre-activations
        gemm_k128<<<dim3(NODES / 64, 3), 256, GEMM_SMEM>>>(agg0, Wi, gi, 384, 384, 128);
        gemm_k128<<<dim3(NODES / 64, 3), 256, GEMM_SMEM>>>(h, Wh, gh, 384, 384, 128);
        gru_elem<<<NODES * 128 / 256, 256>>>(gi, gh, bi, bh, h, mask);
    }

    readout1<<<dim3(16, Bb), 64>>>(h, h0, rmask, Wg, bg, Wo, bo, partial);
    readout2<<<1, 128>>>(partial, out);
}

// round 11
// speedup vs baseline: 1.9705x; 1.4789x over previous
#include <cuda_runtime.h>
#include <cuda_fp16.h>
#include <math.h>

#define Bb 8
#define Nn 1024
#define Ll 5
#define TGT 12
#define NLAYERS 3
#define NODES (Bb * Nn) /* 8192 */
#define KTOT (Ll * Nn)  /* 5120 */

// ---------------- scratch (single __device__ buffer, no allocations) ----------------
#define OFF_H      0
#define OFF_H0     (OFF_H + NODES * 128)
#define OFF_MASK   (OFF_H0 + NODES * 128)
#define OFF_RMASK  (OFF_MASK + NODES)
#define OFF_MCAT   (OFF_RMASK + NODES)                    /* __half[Bb*KTOT*128] */
#define OFF_WCAT   (OFF_MCAT + Bb * KTOT * 128 / 2)       /* __half[Bb*Nn*KTOT]  */
#define OFF_AGG    (OFF_WCAT + Bb * Nn * KTOT / 2)
#define OFF_GI     (OFF_AGG + NODES * 128)
#define OFF_GH     (OFF_GI + NODES * 384)
#define OFF_PART   (OFF_GH + NODES * 384)
#define SCRATCH_FLOATS (OFF_PART + Bb * 16 * TGT)

__device__ float d_scratch[SCRATCH_FLOATS];

__device__ __forceinline__ unsigned smem_u32(const void* p) {
    return (unsigned)__cvta_generic_to_shared(p);
}
#define CP16(dst, src) \
    asm volatile("cp.async.cg.shared.global [%0], [%1], 16;\n" ::"r"(dst), "l"(src))

// ---------------- init ----------------
__global__ void init_pad(const float* __restrict__ h_in, float* __restrict__ h,
                         float* __restrict__ h0) {
    int idx = blockIdx.x * blockDim.x + threadIdx.x;
    int node = idx >> 7;
    int j = idx & 127;
    float v = (j < 64) ? h_in[node * 64 + j] : 0.f;
    h0[idx] = v;
    h[idx] = v;
}

__global__ void init_mask(const float* __restrict__ h_in, float* __restrict__ mask,
                          float* __restrict__ rmask) {
    int node = blockIdx.x * blockDim.x + threadIdx.x;
    float sa = 0.f, s = 0.f;
    const float* row = h_in + node * 64;
    for (int j = 0; j < 64; j++) {
        float v = row[j];
        sa += fabsf(v);
        s += v;
    }
    mask[node] = (sa > 0.f) ? 1.f : 0.f;
    rmask[node] = (s > 0.f) ? 1.f : 0.f;
}

// ---------------- Wcat build (once): Wcat[b][v][l*1024+w] = g*(e==l), fp16 ----------------
__global__ void wcat_build(const float* __restrict__ g, const int* __restrict__ e,
                           __half* __restrict__ Wcat) {
    size_t idx = (size_t)blockIdx.x * 256 + threadIdx.x;  // over Bb*Nn*Nn
    int w = idx & 1023;
    size_t vw = idx >> 10;
    int v = vw & 1023;
    int b = vw >> 10;
    float gv = g[idx];
    int lab = e[idx];
    __half* base = Wcat + ((size_t)b * Nn + v) * KTOT + w;
    __half hg = __float2half(gv);
    __half hz = __float2half(0.f);
#pragma unroll
    for (int l = 0; l < Ll; l++) base[l * Nn] = (l == lab) ? hg : hz;
}

// ---------------- fp32-out GEMM, K=128 (GRU gates) ----------------
__global__ void gemm_k128(const float* __restrict__ A, const float* __restrict__ B,
                          float* __restrict__ C, int ldb, int ldc, int bstride) {
    extern __shared__ float sm[];
    float* As = sm;             // 64*128
    float* Bs = sm + 64 * 128;  // 128*128
    int t = threadIdx.x;
    const float* Bp = B + blockIdx.y * bstride;
    int row0 = blockIdx.x * 64;
    int cbase = blockIdx.y * 128;

#pragma unroll
    for (int i = 0; i < 8; i++) {
        int f = t + i * 256;
        int r = f >> 5;
        int c4 = (f & 31) << 2;
        *(float4*)&As[r * 128 + c4] = *(const float4*)&A[(size_t)(row0 + r) * 128 + c4];
    }
#pragma unroll
    for (int i = 0; i < 16; i++) {
        int f = t + i * 256;
        int k = f >> 5;
        int c4 = (f & 31) << 2;
        *(float4*)&Bs[k * 128 + c4] = *(const float4*)&Bp[(size_t)k * ldb + c4];
    }
    __syncthreads();

    int tcol = (t & 31) << 2;
    int trow = (t >> 5) << 3;
    float4 acc[8];
#pragma unroll
    for (int i = 0; i < 8; i++) acc[i] = make_float4(0.f, 0.f, 0.f, 0.f);

#pragma unroll 2
    for (int k = 0; k < 128; k += 4) {
        float4 b0 = *(float4*)&Bs[(k + 0) * 128 + tcol];
        float4 b1 = *(float4*)&Bs[(k + 1) * 128 + tcol];
        float4 b2 = *(float4*)&Bs[(k + 2) * 128 + tcol];
        float4 b3 = *(float4*)&Bs[(k + 3) * 128 + tcol];
#pragma unroll
        for (int i = 0; i < 8; i++) {
            float4 a = *(float4*)&As[(trow + i) * 128 + k];
            acc[i].x += a.x * b0.x; acc[i].y += a.x * b0.y; acc[i].z += a.x * b0.z; acc[i].w += a.x * b0.w;
            acc[i].x += a.y * b1.x; acc[i].y += a.y * b1.y; acc[i].z += a.y * b1.z; acc[i].w += a.y * b1.w;
            acc[i].x += a.z * b2.x; acc[i].y += a.z * b2.y; acc[i].z += a.z * b2.z; acc[i].w += a.z * b2.w;
            acc[i].x += a.w * b3.x; acc[i].y += a.w * b3.y; acc[i].z += a.w * b3.z; acc[i].w += a.w * b3.w;
        }
    }

#pragma unroll
    for (int i = 0; i < 8; i++) {
        *(float4*)&C[(size_t)(row0 + trow + i) * ldc + cbase + tcol] = acc[i];
    }
}

// ---------------- fp16-out messages GEMM: Mcat[b*KTOT + l*Nn + w][o] = (h @ A_l) ----------------
__global__ void gemm_k128_h(const float* __restrict__ A, const float* __restrict__ B,
                            __half* __restrict__ C, int ldb, int bstride) {
    extern __shared__ float sm[];
    float* As = sm;
    float* Bs = sm + 64 * 128;
    int t = threadIdx.x;
    const float* Bp = B + blockIdx.y * bstride;
    int row0 = blockIdx.x * 64;

#pragma unroll
    for (int i = 0; i < 8; i++) {
        int f = t + i * 256;
        int r = f >> 5;
        int c4 = (f & 31) << 2;
        *(float4*)&As[r * 128 + c4] = *(const float4*)&A[(size_t)(row0 + r) * 128 + c4];
    }
#pragma unroll
    for (int i = 0; i < 16; i++) {
        int f = t + i * 256;
        int k = f >> 5;
        int c4 = (f & 31) << 2;
        *(float4*)&Bs[k * 128 + c4] = *(const float4*)&Bp[(size_t)k * ldb + c4];
    }
    __syncthreads();

    int tcol = (t & 31) << 2;
    int trow = (t >> 5) << 3;
    float4 acc[8];
#pragma unroll
    for (int i = 0; i < 8; i++) acc[i] = make_float4(0.f, 0.f, 0.f, 0.f);

#pragma unroll 2
    for (int k = 0; k < 128; k += 4) {
        float4 b0 = *(float4*)&Bs[(k + 0) * 128 + tcol];
        float4 b1 = *(float4*)&Bs[(k + 1) * 128 + tcol];
        float4 b2 = *(float4*)&Bs[(k + 2) * 128 + tcol];
        float4 b3 = *(float4*)&Bs[(k + 3) * 128 + tcol];
#pragma unroll
        for (int i = 0; i < 8; i++) {
            float4 a = *(float4*)&As[(trow + i) * 128 + k];
            acc[i].x += a.x * b0.x; acc[i].y += a.x * b0.y; acc[i].z += a.x * b0.z; acc[i].w += a.x * b0.w;
            acc[i].x += a.y * b1.x; acc[i].y += a.y * b1.y; acc[i].z += a.y * b1.z; acc[i].w += a.y * b1.w;
            acc[i].x += a.z * b2.x; acc[i].y += a.z * b2.y; acc[i].z += a.z * b2.z; acc[i].w += a.z * b2.w;
            acc[i].x += a.w * b3.x; acc[i].y += a.w * b3.y; acc[i].z += a.w * b3.z; acc[i].w += a.w * b3.w;
        }
    }

#pragma unroll
    for (int i = 0; i < 8; i++) {
        int node = row0 + trow + i;
        size_t orow = (size_t)(node >> 10) * KTOT + (size_t)blockIdx.y * Nn + (node & 1023);
        __half2 p0 = __floats2half2_rn(acc[i].x, acc[i].y);
        __half2 p1 = __floats2half2_rn(acc[i].z, acc[i].w);
        uint2 u;
        u.x = *(unsigned*)&p0;
        u.y = *(unsigned*)&p1;
        *(uint2*)&C[orow * 128 + tcol] = u;
    }
}

// ---------------- tensor-core aggregation: agg[b] = Wcat[b] @ Mcat[b]  (M=1024,N=128,K=5120) ----
// grid (16, 8), block 256 (8 warps: 4m x 2n). CTA tile 64v x 128o.
#define AS_STRIDE 72   /* 64 + 8 pad halves; 144B rows */
#define BS_STRIDE 136  /* 128 + 8 pad halves; 272B rows */
#define AS_ELEMS (64 * AS_STRIDE)
#define BS_ELEMS (64 * BS_STRIDE)
#define NKSTEP 80      /* 5120 / 64 */

__device__ __forceinline__ void mma_load_tiles(int s, int kc, int t,
                                               const __half* Ag, const __half* Bg,
                                               __half* As, __half* Bs) {
#pragma unroll
    for (int i = 0; i < 2; i++) {
        int c = t + i * 256;          // 512 chunks of 16B for A (64 x 64 halves)
        int row = c >> 3;
        int ch = (c & 7) * 8;
        unsigned dst = smem_u32(As + s * AS_ELEMS + row * AS_STRIDE + ch);
        const __half* src = Ag + (size_t)row * KTOT + kc * 64 + ch;
        CP16(dst, src);
    }
#pragma unroll
    for (int i = 0; i < 4; i++) {
        int c = t + i * 256;          // 1024 chunks for B (64 x 128 halves)
        int row = c >> 4;
        int ch = (c & 15) * 8;
        unsigned dst = smem_u32(Bs + s * BS_ELEMS + row * BS_STRIDE + ch);
        const __half* src = Bg + (size_t)(kc * 64 + row) * 128 + ch;
        CP16(dst, src);
    }
    asm volatile("cp.async.commit_group;\n" ::);
}

__global__ __launch_bounds__(256, 2) void mma_gather(const __half* __restrict__ Wcat,
                                                     const __half* __restrict__ Mcat,
                                                     float* __restrict__ agg) {
    extern __shared__ __half dynsm[];
    __half* As = dynsm;                  // [2][64][AS_STRIDE]
    __half* Bs = dynsm + 2 * AS_ELEMS;   // [2][64][BS_STRIDE]
    int t = threadIdx.x;
    int lane = t & 31, warp = t >> 5;
    int wm = warp & 3, wn = warp >> 2;
    int b = blockIdx.y, v0 = blockIdx.x * 64;

    const __half* Ag = Wcat + ((size_t)b * Nn + v0) * KTOT;
    const __half* Bg = Mcat + (size_t)b * KTOT * 128;

    float acc[8][4];
#pragma unroll
    for (int j = 0; j < 8; j++)
#pragma unroll
        for (int q = 0; q < 4; q++) acc[j][q] = 0.f;

    mma_load_tiles(0, 0, t, Ag, Bg, As, Bs);
    int s = 0;
    int ga = lane >> 3;                // ldmatrix group 0..3
    int grow = (ga & 1) * 8 + (lane & 7);
    int gcol = (ga >> 1) * 8;

    for (int kc = 0; kc < NKSTEP; kc++) {
        if (kc < NKSTEP - 1) {
            mma_load_tiles(s ^ 1, kc + 1, t, Ag, Bg, As, Bs);
            asm volatile("cp.async.wait_group 1;\n" ::);
        } else {
            asm volatile("cp.async.wait_group 0;\n" ::);
        }
        __syncthreads();

        const __half* Asb = As + s * AS_ELEMS;
        const __half* Bsb = Bs + s * BS_ELEMS;
#pragma unroll
        for (int k16 = 0; k16 < 4; k16++) {
            int k0 = k16 * 16;
            unsigned a0, a1, a2, a3;
            unsigned aaddr = smem_u32(Asb + (wm * 16 + grow) * AS_STRIDE + k0 + gcol);
            asm volatile("ldmatrix.sync.aligned.m8n8.x4.shared.b16 {%0,%1,%2,%3}, [%4];\n"
                         : "=r"(a0), "=r"(a1), "=r"(a2), "=r"(a3)
                         : "r"(aaddr));
#pragma unroll
            for (int nb = 0; nb < 4; nb++) {
                unsigned b0, b1, b2, b3;
                int n0 = wn * 64 + nb * 16;
                unsigned baddr = smem_u32(Bsb + (k0 + grow) * BS_STRIDE + n0 + gcol);
                asm volatile("ldmatrix.sync.aligned.m8n8.x4.trans.shared.b16 {%0,%1,%2,%3}, [%4];\n"
                             : "=r"(b0), "=r"(b1), "=r"(b2), "=r"(b3)
                             : "r"(baddr));
                int j0 = nb * 2;
                asm volatile(
                    "mma.sync.aligned.m16n8k16.row.col.f32.f16.f16.f32 "
                    "{%0,%1,%2,%3}, {%4,%5,%6,%7}, {%8,%9}, {%0,%1,%2,%3};\n"
                    : "+f"(acc[j0][0]), "+f"(acc[j0][1]), "+f"(acc[j0][2]), "+f"(acc[j0][3])
                    : "r"(a0), "r"(a1), "r"(a2), "r"(a3), "r"(b0), "r"(b1));
                asm volatile(
                    "mma.sync.aligned.m16n8k16.row.col.f32.f16.f16.f32 "
                    "{%0,%1,%2,%3}, {%4,%5,%6,%7}, {%8,%9}, {%0,%1,%2,%3};\n"
                    : "+f"(acc[j0 + 1][0]), "+f"(acc[j0 + 1][1]), "+f"(acc[j0 + 1][2]), "+f"(acc[j0 + 1][3])
                    : "r"(a0), "r"(a1), "r"(a2), "r"(a3), "r"(b2), "r"(b3));
            }
        }
        __syncthreads();
        s ^= 1;
    }

    // epilogue: D rows v0 + wm*16 + lane/4 (+8), cols wn*64 + j*8 + (lane&3)*2
    int r0 = v0 + wm * 16 + (lane >> 2);
#pragma unroll
    for (int j = 0; j < 8; j++) {
        int col = wn * 64 + j * 8 + (lane & 3) * 2;
        float2 lo = make_float2(acc[j][0], acc[j][1]);
        float2 hi = make_float2(acc[j][2], acc[j][3]);
        *(float2*)&agg[((size_t)b * Nn + r0) * 128 + col] = lo;
        *(float2*)&agg[((size_t)b * Nn + r0 + 8) * 128 + col] = hi;
    }
}

// ---------------- GRU elementwise ----------------
__global__ void gru_elem(const float* __restrict__ gi, const float* __restrict__ gh,
                         const float* __restrict__ bi, const float* __restrict__ bh,
                         float* __restrict__ h, const float* __restrict__ mask) {
    int idx = blockIdx.x * blockDim.x + threadIdx.x;
    int node = idx >> 7;
    int j = idx & 127;
    size_t base = (size_t)node * 384;
    float ir = gi[base + j] + bi[j];
    float iz = gi[base + 128 + j] + bi[128 + j];
    float in_ = gi[base + 256 + j] + bi[256 + j];
    float hr = gh[base + j] + bh[j];
    float hz = gh[base + 128 + j] + bh[128 + j];
    float hn = gh[base + 256 + j] + bh[256 + j];
    float r = 1.f / (1.f + expf(-(ir + hr)));
    float z = 1.f / (1.f + expf(-(iz + hz)));
    float n = tanhf(in_ + r * hn);
    float hv = h[idx];
    h[idx] = ((1.f - z) * n + z * hv) * mask[node];
}

// ---------------- readout ----------------
__global__ void readout1(const float* __restrict__ h, const float* __restrict__ h0,
                         const float* __restrict__ rmask, const float* __restrict__ Wg,
                         const float* __restrict__ bg, const float* __restrict__ Wo,
                         const float* __restrict__ bo, float* __restrict__ partial) {
    __shared__ float red[64][TGT];
    int b = blockIdx.y;
    int node = b * Nn + blockIdx.x * 64 + threadIdx.x;
    const float* hT = &h[(size_t)node * 128];
    const float* hz = &h0[(size_t)node * 128];
    float rm = rmask[node];

    float sg[TGT], so[TGT];
#pragma unroll
    for (int t = 0; t < TGT; t++) { sg[t] = bg[t]; so[t] = bo[t]; }

    for (int j = 0; j < 128; j++) {
        float a = hT[j];
        float c = hz[j];
#pragma unroll
        for (int t = 0; t < TGT; t++) {
            sg[t] += a * Wg[j * TGT + t] + c * Wg[(128 + j) * TGT + t];
            so[t] += a * Wo[j * TGT + t];
        }
    }
#pragma unroll
    for (int t = 0; t < TGT; t++) {
        float gate = 1.f / (1.f + expf(-sg[t]));
        red[threadIdx.x][t] = gate * so[t] * rm;
    }
    __syncthreads();
    if (threadIdx.x < TGT) {
        int t = threadIdx.x;
        float s = 0.f;
        for (int v = 0; v < 64; v++) s += red[v][t];
        partial[((size_t)b * 16 + blockIdx.x) * TGT + t] = s;
    }
}

__global__ void readout2(const float* __restrict__ partial, float* __restrict__ out) {
    int i = threadIdx.x;
    if (i < Bb * TGT) {
        int b = i / TGT, t = i % TGT;
        float s = 0.f;
        for (int c = 0; c < 16; c++) s += partial[((size_t)b * 16 + c) * TGT + t];
        out[i] = s;
    }
}

// ---------------- launch ----------------
extern "C" void kernel_launch(void* const* d_in, const int* in_sizes, int n_in,
                              void* d_out, int out_size) {
    const float* g = (const float*)d_in[0];
    const float* h_in = (const float*)d_in[1];
    const int* e = (const int*)d_in[2];
    const float* A = (const float*)d_in[3];
    const float* Wi = (const float*)d_in[4];
    const float* Wh = (const float*)d_in[5];
    const float* bi = (const float*)d_in[6];
    const float* bh = (const float*)d_in[7];
    const float* Wg = (const float*)d_in[8];
    const float* bg = (const float*)d_in[9];
    const float* Wo = (const float*)d_in[10];
    const float* bo = (const float*)d_in[11];
    float* out = (float*)d_out;

    float* base;
    cudaGetSymbolAddress((void**)&base, d_scratch);
    float* h = base + OFF_H;
    float* h0 = base + OFF_H0;
    float* mask = base + OFF_MASK;
    float* rmask = base + OFF_RMASK;
    __half* Mcat = (__half*)(base + OFF_MCAT);
    __half* Wcat = (__half*)(base + OFF_WCAT);
    float* agg = base + OFF_AGG;
    float* gi = base + OFF_GI;
    float* gh = base + OFF_GH;
    float* partial = base + OFF_PART;

    const int GEMM_SMEM = (64 * 128 + 128 * 128) * 4;                   // 96KB
    const int MMA_SMEM = 2 * (AS_ELEMS + BS_ELEMS) * (int)sizeof(__half);  // 53248B
    cudaFuncSetAttribute(gemm_k128, cudaFuncAttributeMaxDynamicSharedMemorySize, GEMM_SMEM);
    cudaFuncSetAttribute(gemm_k128_h, cudaFuncAttributeMaxDynamicSharedMemorySize, GEMM_SMEM);
    cudaFuncSetAttribute(mma_gather, cudaFuncAttributeMaxDynamicSharedMemorySize, MMA_SMEM);

    init_pad<<<NODES * 128 / 256, 256>>>(h_in, h, h0);
    init_mask<<<NODES / 128, 128>>>(h_in, mask, rmask);
    wcat_build<<<Bb * Nn * Nn / 256, 256>>>(g, e, Wcat);

    for (int layer = 0; layer < NLAYERS; layer++) {
        // messages -> Mcat[b][l*1024+w][o] fp16
        gemm_k128_h<<<dim3(NODES / 64, Ll), 256, GEMM_SMEM>>>(h, A, Mcat, 128, 128 * 128);
        // aggregation on tensor cores: agg[b] = Wcat[b] @ Mcat[b]
        mma_gather<<<dim3(Nn / 64, Bb), 256, MMA_SMEM>>>(Wcat, Mcat, agg);
        // GRU gate pre-activations
        gemm_k128<<<dim3(NODES / 64, 3), 256, GEMM_SMEM>>>(agg, Wi, gi, 384, 384, 128);
        gemm_k128<<<dim3(NODES / 64, 3), 256, GEMM_SMEM>>>(h, Wh, gh, 384, 384, 128);
        gru_elem<<<NODES * 128 / 256, 256>>>(gi, gh, bi, bh, h, mask);
    }

    readout1<<<dim3(16, Bb), 64>>>(h, h0, rmask, Wg, bg, Wo, bo, partial);
    readout2<<<1, 128>>>(partial, out);
}